// round 7
// baseline (speedup 1.0000x reference)
#include <cuda_runtime.h>

// Fused 2-layer LSTM + FC for B=4096, T=256, IN=16, H1=64, H2=1 (fp32).
// K-split GEMV (unchanged from R6) + tanh.approx activations + layer-2 step
// spread across all 256 threads (shfl reduction).

#define BG 16
#define NT 256
#define HXW 84   // hx row stride in floats
typedef unsigned long long u64;

__device__ __forceinline__ void fma2(u64 &acc, u64 a, u64 b) {
    asm("fma.rn.f32x2 %0, %1, %2, %0;" : "+l"(acc) : "l"(a), "l"(b));
}
__device__ __forceinline__ float lo_f(u64 v) { return __uint_as_float((unsigned)v); }
__device__ __forceinline__ float hi_f(u64 v) { return __uint_as_float((unsigned)(v >> 32)); }
__device__ __forceinline__ float tanh_ap(float x) {
    float y; asm("tanh.approx.f32 %0, %1;" : "=f"(y) : "f"(x)); return y;
}
__device__ __forceinline__ float sig_ap(float x) {
    return fmaf(0.5f, tanh_ap(0.5f * x), 0.5f);
}

__global__ void __launch_bounds__(NT, 2) lstm_fused(
    const float* __restrict__ x,
    const float* __restrict__ wih1, const float* __restrict__ whh1,
    const float* __restrict__ bih1, const float* __restrict__ bhh1,
    const float* __restrict__ wih2, const float* __restrict__ whh2,
    const float* __restrict__ bih2, const float* __restrict__ bhh2,
    const float* __restrict__ fcw, const float* __restrict__ fcb,
    float* __restrict__ out)
{
    __shared__ __align__(16) float sgP[2][256][BG + 1]; // partial gate sums (khalf 0/1)
    __shared__ __align__(16) float hx_s[BG][HXW];       // [0:16)=x(t), [16:80)=h(t-1)
    __shared__ __align__(16) float c_s[BG][64];         // layer1 cell state
    __shared__ __align__(16) float w2_s[4][66];         // layer2 input weights
    __shared__ float b2_s[4], whh2_s[4], fc_s[2];
    __shared__ float h2_s[BG], c2_s[BG];

    const int tid = threadIdx.x;
    const int b0 = blockIdx.x * BG;
    const int r = tid & 127;          // row pair (r, r+128)
    const int khalf = tid >> 7;       // 0: floats [0,40)  1: floats [40,80)
    const int koff = khalf * 40;

    // ---- per-thread layer1 weights: 20 u64 per row, rows r and r+128 ----
    u64 wA[20], wB[20];
    if (khalf == 0) {
        const u64* wiA = (const u64*)(wih1 + r * 16);
        const u64* wiB = (const u64*)(wih1 + (r + 128) * 16);
        const u64* whA = (const u64*)(whh1 + r * 64);
        const u64* whB = (const u64*)(whh1 + (r + 128) * 64);
        #pragma unroll
        for (int m = 0; m < 8; m++)  { wA[m] = wiA[m]; wB[m] = wiB[m]; }
        #pragma unroll
        for (int m = 8; m < 20; m++) { wA[m] = whA[m - 8]; wB[m] = whB[m - 8]; }
    } else {
        const u64* whA = (const u64*)(whh1 + r * 64);
        const u64* whB = (const u64*)(whh1 + (r + 128) * 64);
        #pragma unroll
        for (int m = 0; m < 20; m++) { wA[m] = whA[m + 12]; wB[m] = whB[m + 12]; }
    }
    const u64 initA = khalf ? 0ull : (u64)__float_as_uint(bih1[r] + bhh1[r]);
    const u64 initB = khalf ? 0ull : (u64)__float_as_uint(bih1[r + 128] + bhh1[r + 128]);

    // ---- smem init ----
    for (int i = tid; i < 4 * 64; i += NT) w2_s[i >> 6][i & 63] = wih2[i];
    if (tid < 4) { b2_s[tid] = bih2[tid] + bhh2[tid]; whh2_s[tid] = whh2[tid]; }
    if (tid == 0) { fc_s[0] = fcw[0]; fc_s[1] = fcb[0]; }
    for (int i = tid; i < BG * 64; i += NT) c_s[i >> 6][i & 63] = 0.f;
    for (int i = tid; i < BG * HXW; i += NT) hx_s[i / HXW][i % HXW] = 0.f;
    if (tid < BG) { h2_s[tid] = 0.f; c2_s[tid] = 0.f; }
    __syncthreads();

    // ---- layer2 per-thread constants: g2 = (b2i, j2), k-quarter kq2 ----
    const int g2 = tid >> 2, b2i = g2 >> 2, j2 = g2 & 3, kq2 = tid & 3;
    const int laneid = tid & 31;
    const u64 init2 = (kq2 == 0) ? (u64)__float_as_uint(b2_s[j2]) : 0ull;
    const float w2h0 = whh2_s[0], w2h1 = whh2_s[1], w2h2 = whh2_s[2], w2h3 = whh2_s[3];
    const float fc0 = fc_s[0], fc1 = fc_s[1];

    // ---- x staging ----
    const int bq = tid >> 4, kq = tid & 15;
    const float* xptr = x + (long)(b0 + bq) * 4096 + kq;
    hx_s[bq][kq] = xptr[0];
    float xr = xptr[16];

    __syncthreads();

    for (int t = 0; t < 256; ++t) {
        // ===== layer1 gate GEMV: 2 rows x 40 k x 16 batches per thread =====
        #pragma unroll 1
        for (int bb = 0; bb < BG; bb += 4) {
            u64 aA0 = initA, aA1 = initA, aA2 = initA, aA3 = initA;
            u64 aB0 = initB, aB1 = initB, aB2 = initB, aB3 = initB;
            const float* h0 = &hx_s[bb + 0][koff];
            const float* h1 = &hx_s[bb + 1][koff];
            const float* h2 = &hx_s[bb + 2][koff];
            const float* h3 = &hx_s[bb + 3][koff];
            #pragma unroll
            for (int q = 0; q < 10; q++) {
                const u64 w0 = wA[2 * q], w1 = wA[2 * q + 1];
                const u64 u0 = wB[2 * q], u1 = wB[2 * q + 1];
                ulonglong2 v0 = *(const ulonglong2*)(h0 + q * 4);
                ulonglong2 v1 = *(const ulonglong2*)(h1 + q * 4);
                ulonglong2 v2 = *(const ulonglong2*)(h2 + q * 4);
                ulonglong2 v3 = *(const ulonglong2*)(h3 + q * 4);
                fma2(aA0, w0, v0.x); fma2(aA0, w1, v0.y);
                fma2(aB0, u0, v0.x); fma2(aB0, u1, v0.y);
                fma2(aA1, w0, v1.x); fma2(aA1, w1, v1.y);
                fma2(aB1, u0, v1.x); fma2(aB1, u1, v1.y);
                fma2(aA2, w0, v2.x); fma2(aA2, w1, v2.y);
                fma2(aB2, u0, v2.x); fma2(aB2, u1, v2.y);
                fma2(aA3, w0, v3.x); fma2(aA3, w1, v3.y);
                fma2(aB3, u0, v3.x); fma2(aB3, u1, v3.y);
            }
            sgP[khalf][r][bb + 0] = lo_f(aA0) + hi_f(aA0);
            sgP[khalf][r][bb + 1] = lo_f(aA1) + hi_f(aA1);
            sgP[khalf][r][bb + 2] = lo_f(aA2) + hi_f(aA2);
            sgP[khalf][r][bb + 3] = lo_f(aA3) + hi_f(aA3);
            sgP[khalf][128 + r][bb + 0] = lo_f(aB0) + hi_f(aB0);
            sgP[khalf][128 + r][bb + 1] = lo_f(aB1) + hi_f(aB1);
            sgP[khalf][128 + r][bb + 2] = lo_f(aB2) + hi_f(aB2);
            sgP[khalf][128 + r][bb + 3] = lo_f(aB3) + hi_f(aB3);
        }
        __syncthreads();   // A: partial gates staged

        // ===== layer1 activations + state update (tanh.approx) =====
        {
            const int u = tid & 63;
            const int bgrp = tid >> 6;
            #pragma unroll
            for (int j = 0; j < 4; ++j) {
                const int b = bgrp * 4 + j;
                float gi = sgP[0][u][b]       + sgP[1][u][b];
                float gf = sgP[0][64 + u][b]  + sgP[1][64 + u][b];
                float gg = sgP[0][128 + u][b] + sgP[1][128 + u][b];
                float go = sgP[0][192 + u][b] + sgP[1][192 + u][b];
                float i_ = sig_ap(gi), f_ = sig_ap(gf);
                float g_ = tanh_ap(gg), o_ = sig_ap(go);
                float c = f_ * c_s[b][u] + i_ * g_;
                c_s[b][u] = c;
                hx_s[b][16 + u] = o_ * tanh_ap(c);
            }
            if (t < 255) hx_s[bq][kq] = xr;
            if (t < 254) xr = xptr[(t + 2) * 16];
        }
        __syncthreads();   // B: h(t) and x(t+1) ready

        // ===== layer2 LSTM step + FC (all 256 threads, shfl reduce) =====
        {
            u64 acc = init2;
            const u64* wrow = (const u64*)&w2_s[j2][kq2 * 16];
            const u64* hb = (const u64*)&hx_s[b2i][16 + kq2 * 16];
            #pragma unroll
            for (int q = 0; q < 8; q++) fma2(acc, wrow[q], hb[q]);
            float p = lo_f(acc) + hi_f(acc);
            p += __shfl_xor_sync(0xffffffffu, p, 1);
            p += __shfl_xor_sync(0xffffffffu, p, 2);   // sum over kq2
            const int base = laneid & ~15;             // batch subgroup base lane
            float gi = __shfl_sync(0xffffffffu, p, base + 0);
            float gf = __shfl_sync(0xffffffffu, p, base + 4);
            float gg = __shfl_sync(0xffffffffu, p, base + 8);
            float go = __shfl_sync(0xffffffffu, p, base + 12);
            if ((laneid & 15) == 0) {
                float h2p = h2_s[b2i];
                gi += w2h0 * h2p; gf += w2h1 * h2p;
                gg += w2h2 * h2p; go += w2h3 * h2p;
                float i_ = sig_ap(gi), f_ = sig_ap(gf);
                float g_ = tanh_ap(gg), o_ = sig_ap(go);
                float c2 = f_ * c2_s[b2i] + i_ * g_;
                c2_s[b2i] = c2;
                float h2v = o_ * tanh_ap(c2);
                h2_s[b2i] = h2v;
                out[(long)(b0 + b2i) * 256 + t] = fc0 * h2v + fc1;
            }
        }
        // next step's barrier A orders hx/h2/c2 writes vs. these reads
    }
}

extern "C" void kernel_launch(void* const* d_in, const int* in_sizes, int n_in,
                              void* d_out, int out_size) {
    (void)in_sizes; (void)n_in; (void)out_size;
    const float* x    = (const float*)d_in[0];
    const float* wih1 = (const float*)d_in[1];
    const float* whh1 = (const float*)d_in[2];
    const float* bih1 = (const float*)d_in[3];
    const float* bhh1 = (const float*)d_in[4];
    const float* wih2 = (const float*)d_in[5];
    const float* whh2 = (const float*)d_in[6];
    const float* bih2 = (const float*)d_in[7];
    const float* bhh2 = (const float*)d_in[8];
    const float* fcw  = (const float*)d_in[9];
    const float* fcb  = (const float*)d_in[10];
    float* out = (float*)d_out;

    lstm_fused<<<4096 / BG, NT>>>(x, wih1, whh1, bih1, bhh1,
                                  wih2, whh2, bih2, bhh2, fcw, fcb, out);
}

// round 12
// speedup vs baseline: 1.2021x; 1.2021x over previous
#include <cuda_runtime.h>

// Fused 2-layer LSTM + FC for B=4096, T=256, IN=16, H1=64, H2=1 (fp32).
// BG=14 x 293 CTAs -> fills 147/148 SMs at 2 CTAs/SM (was 128/148).
// K-split GEMV (2 rows x 40 k per thread, packed f32x2), tanh.approx
// activations, layer-2 on 64 threads only (others run ahead -> overlap).

#define BG 14
#define NT 256
#define HXW 84   // hx row stride in floats
typedef unsigned long long u64;

__device__ __forceinline__ void fma2(u64 &acc, u64 a, u64 b) {
    asm("fma.rn.f32x2 %0, %1, %2, %0;" : "+l"(acc) : "l"(a), "l"(b));
}
__device__ __forceinline__ float lo_f(u64 v) { return __uint_as_float((unsigned)v); }
__device__ __forceinline__ float hi_f(u64 v) { return __uint_as_float((unsigned)(v >> 32)); }
__device__ __forceinline__ float tanh_ap(float x) {
    float y; asm("tanh.approx.f32 %0, %1;" : "=f"(y) : "f"(x)); return y;
}
__device__ __forceinline__ float sig_ap(float x) {
    return fmaf(0.5f, tanh_ap(0.5f * x), 0.5f);
}

#define GEMV_BLOCK4(BB)                                                        \
    do {                                                                       \
        u64 aA0 = initA, aA1 = initA, aA2 = initA, aA3 = initA;                \
        u64 aB0 = initB, aB1 = initB, aB2 = initB, aB3 = initB;                \
        const float* h0 = &hx_s[(BB) + 0][koff];                               \
        const float* h1 = &hx_s[(BB) + 1][koff];                               \
        const float* h2 = &hx_s[(BB) + 2][koff];                               \
        const float* h3 = &hx_s[(BB) + 3][koff];                               \
        _Pragma("unroll")                                                      \
        for (int q = 0; q < 10; q++) {                                         \
            const u64 w0 = wA[2 * q], w1 = wA[2 * q + 1];                      \
            const u64 u0 = wB[2 * q], u1 = wB[2 * q + 1];                      \
            ulonglong2 v0 = *(const ulonglong2*)(h0 + q * 4);                  \
            ulonglong2 v1 = *(const ulonglong2*)(h1 + q * 4);                  \
            ulonglong2 v2 = *(const ulonglong2*)(h2 + q * 4);                  \
            ulonglong2 v3 = *(const ulonglong2*)(h3 + q * 4);                  \
            fma2(aA0, w0, v0.x); fma2(aA0, w1, v0.y);                          \
            fma2(aB0, u0, v0.x); fma2(aB0, u1, v0.y);                          \
            fma2(aA1, w0, v1.x); fma2(aA1, w1, v1.y);                          \
            fma2(aB1, u0, v1.x); fma2(aB1, u1, v1.y);                          \
            fma2(aA2, w0, v2.x); fma2(aA2, w1, v2.y);                          \
            fma2(aB2, u0, v2.x); fma2(aB2, u1, v2.y);                          \
            fma2(aA3, w0, v3.x); fma2(aA3, w1, v3.y);                          \
            fma2(aB3, u0, v3.x); fma2(aB3, u1, v3.y);                          \
        }                                                                      \
        sgP[khalf][r][(BB) + 0] = lo_f(aA0) + hi_f(aA0);                       \
        sgP[khalf][r][(BB) + 1] = lo_f(aA1) + hi_f(aA1);                       \
        sgP[khalf][r][(BB) + 2] = lo_f(aA2) + hi_f(aA2);                       \
        sgP[khalf][r][(BB) + 3] = lo_f(aA3) + hi_f(aA3);                       \
        sgP[khalf][128 + r][(BB) + 0] = lo_f(aB0) + hi_f(aB0);                 \
        sgP[khalf][128 + r][(BB) + 1] = lo_f(aB1) + hi_f(aB1);                 \
        sgP[khalf][128 + r][(BB) + 2] = lo_f(aB2) + hi_f(aB2);                 \
        sgP[khalf][128 + r][(BB) + 3] = lo_f(aB3) + hi_f(aB3);                 \
    } while (0)

#define GEMV_BLOCK2(BB)                                                        \
    do {                                                                       \
        u64 aA0 = initA, aA1 = initA;                                          \
        u64 aB0 = initB, aB1 = initB;                                          \
        const float* h0 = &hx_s[(BB) + 0][koff];                               \
        const float* h1 = &hx_s[(BB) + 1][koff];                               \
        _Pragma("unroll")                                                      \
        for (int q = 0; q < 10; q++) {                                         \
            const u64 w0 = wA[2 * q], w1 = wA[2 * q + 1];                      \
            const u64 u0 = wB[2 * q], u1 = wB[2 * q + 1];                      \
            ulonglong2 v0 = *(const ulonglong2*)(h0 + q * 4);                  \
            ulonglong2 v1 = *(const ulonglong2*)(h1 + q * 4);                  \
            fma2(aA0, w0, v0.x); fma2(aA0, w1, v0.y);                          \
            fma2(aB0, u0, v0.x); fma2(aB0, u1, v0.y);                          \
            fma2(aA1, w0, v1.x); fma2(aA1, w1, v1.y);                          \
            fma2(aB1, u0, v1.x); fma2(aB1, u1, v1.y);                          \
        }                                                                      \
        sgP[khalf][r][(BB) + 0] = lo_f(aA0) + hi_f(aA0);                       \
        sgP[khalf][r][(BB) + 1] = lo_f(aA1) + hi_f(aA1);                       \
        sgP[khalf][128 + r][(BB) + 0] = lo_f(aB0) + hi_f(aB0);                 \
        sgP[khalf][128 + r][(BB) + 1] = lo_f(aB1) + hi_f(aB1);                 \
    } while (0)

__global__ void __launch_bounds__(NT, 2) lstm_fused(
    const float* __restrict__ x,
    const float* __restrict__ wih1, const float* __restrict__ whh1,
    const float* __restrict__ bih1, const float* __restrict__ bhh1,
    const float* __restrict__ wih2, const float* __restrict__ whh2,
    const float* __restrict__ bih2, const float* __restrict__ bhh2,
    const float* __restrict__ fcw, const float* __restrict__ fcb,
    float* __restrict__ out)
{
    __shared__ __align__(16) float sgP[2][256][BG + 1]; // partial gate sums
    __shared__ __align__(16) float hx_s[BG][HXW];       // [0:16)=x(t), [16:80)=h(t-1)
    __shared__ __align__(16) float c_s[BG][64];         // layer1 cell state
    __shared__ __align__(16) float w2_s[4][66];         // layer2 input weights
    __shared__ float b2_s[4], whh2_s[4], fc_s[2];
    __shared__ float h2_s[BG], c2_s[BG];

    const int tid = threadIdx.x;
    const int b0 = blockIdx.x * BG;
    const int nb = (4096 - b0 < BG) ? (4096 - b0) : BG;   // valid batches (tail CTA)
    const int r = tid & 127;          // row pair (r, r+128)
    const int khalf = tid >> 7;       // 0: floats [0,40)  1: [40,80)
    const int koff = khalf * 40;

    // ---- per-thread layer1 weights: 20 u64 per row, rows r and r+128 ----
    u64 wA[20], wB[20];
    if (khalf == 0) {
        const u64* wiA = (const u64*)(wih1 + r * 16);
        const u64* wiB = (const u64*)(wih1 + (r + 128) * 16);
        const u64* whA = (const u64*)(whh1 + r * 64);
        const u64* whB = (const u64*)(whh1 + (r + 128) * 64);
        #pragma unroll
        for (int m = 0; m < 8; m++)  { wA[m] = wiA[m]; wB[m] = wiB[m]; }
        #pragma unroll
        for (int m = 8; m < 20; m++) { wA[m] = whA[m - 8]; wB[m] = whB[m - 8]; }
    } else {
        const u64* whA = (const u64*)(whh1 + r * 64);
        const u64* whB = (const u64*)(whh1 + (r + 128) * 64);
        #pragma unroll
        for (int m = 0; m < 20; m++) { wA[m] = whA[m + 12]; wB[m] = whB[m + 12]; }
    }
    const u64 initA = khalf ? 0ull : (u64)__float_as_uint(bih1[r] + bhh1[r]);
    const u64 initB = khalf ? 0ull : (u64)__float_as_uint(bih1[r + 128] + bhh1[r + 128]);

    // ---- smem init ----
    for (int i = tid; i < 4 * 64; i += NT) w2_s[i >> 6][i & 63] = wih2[i];
    if (tid < 4) { b2_s[tid] = bih2[tid] + bhh2[tid]; whh2_s[tid] = whh2[tid]; }
    if (tid == 0) { fc_s[0] = fcw[0]; fc_s[1] = fcb[0]; }
    for (int i = tid; i < BG * 64; i += NT) c_s[i >> 6][i & 63] = 0.f;
    for (int i = tid; i < BG * HXW; i += NT) hx_s[i / HXW][i % HXW] = 0.f;
    if (tid < BG) { h2_s[tid] = 0.f; c2_s[tid] = 0.f; }
    __syncthreads();

    // ---- x staging: thread (bq = tid>>4, kq = tid&15) owns one element/step ----
    const int bq = tid >> 4, kq = tid & 15;            // bq in 0..15
    const int bqv = (bq < nb);                         // valid stager?
    const int bqc = bqv ? bq : 0;                      // clamped (safe address)
    const float* xptr = x + (long)(b0 + bqc) * 4096 + kq;
    if (bqv) hx_s[bq][kq] = xptr[0];
    float xr = xptr[16];

    __syncthreads();

    for (int t = 0; t < 256; ++t) {
        // ===== layer1 gate GEMV: 2 rows x 40 k x 14 batches per thread =====
        GEMV_BLOCK4(0);
        GEMV_BLOCK4(4);
        GEMV_BLOCK4(8);
        GEMV_BLOCK2(12);
        __syncthreads();   // A: partial gates staged

        // ===== layer1 activations + state update (tanh.approx) =====
        {
            const int u = tid & 63;
            const int bgrp = tid >> 6;
            #pragma unroll
            for (int j = 0; j < 4; ++j) {
                const int b = bgrp * 4 + j;            // 0..15
                if (b < BG) {
                    float gi = sgP[0][u][b]       + sgP[1][u][b];
                    float gf = sgP[0][64 + u][b]  + sgP[1][64 + u][b];
                    float gg = sgP[0][128 + u][b] + sgP[1][128 + u][b];
                    float go = sgP[0][192 + u][b] + sgP[1][192 + u][b];
                    float i_ = sig_ap(gi), f_ = sig_ap(gf);
                    float g_ = tanh_ap(gg), o_ = sig_ap(go);
                    float c = f_ * c_s[b][u] + i_ * g_;
                    c_s[b][u] = c;
                    hx_s[b][16 + u] = o_ * tanh_ap(c);
                }
            }
            // stage x for t+1, prefetch t+2
            if (bqv && t < 255) hx_s[bq][kq] = xr;
            if (t < 254) xr = xptr[(t + 2) * 16];
        }
        __syncthreads();   // B: h(t) and x(t+1) ready

        // ===== layer2 LSTM step + FC (threads 0..63 only; others run ahead) =====
        if (tid < 64) {
            const int j = tid & 3;                    // gate i,f,g,o
            const int b = tid >> 2;                   // 0..15
            const int bc = (b < BG) ? b : 0;          // clamp for safe smem reads
            u64 acc = (u64)__float_as_uint(b2_s[j]);
            const u64* wrow = (const u64*)&w2_s[j][0];
            const float* hb = &hx_s[bc][16];
            #pragma unroll
            for (int q = 0; q < 32; q++) {
                u64 hv = *(const u64*)&hb[q * 2];
                fma2(acc, wrow[q], hv);
            }
            float gj = lo_f(acc) + hi_f(acc) + whh2_s[j] * h2_s[bc];
            const int lb = (tid & 31) & ~3;
            float gi = __shfl_sync(0xffffffffu, gj, lb + 0);
            float gf = __shfl_sync(0xffffffffu, gj, lb + 1);
            float gg = __shfl_sync(0xffffffffu, gj, lb + 2);
            float go = __shfl_sync(0xffffffffu, gj, lb + 3);
            if (j == 0 && b < nb) {
                float i_ = sig_ap(gi), f_ = sig_ap(gf);
                float g_ = tanh_ap(gg), o_ = sig_ap(go);
                float c2 = f_ * c2_s[b] + i_ * g_;
                c2_s[b] = c2;
                float h2v = o_ * tanh_ap(c2);
                h2_s[b] = h2v;
                out[(long)(b0 + b) * 256 + t] = fc_s[0] * h2v + fc_s[1];
            }
        }
        // next step's barrier A orders hx/h2/c2 writes vs. these reads
    }
}

extern "C" void kernel_launch(void* const* d_in, const int* in_sizes, int n_in,
                              void* d_out, int out_size) {
    (void)in_sizes; (void)n_in; (void)out_size;
    const float* x    = (const float*)d_in[0];
    const float* wih1 = (const float*)d_in[1];
    const float* whh1 = (const float*)d_in[2];
    const float* bih1 = (const float*)d_in[3];
    const float* bhh1 = (const float*)d_in[4];
    const float* wih2 = (const float*)d_in[5];
    const float* whh2 = (const float*)d_in[6];
    const float* bih2 = (const float*)d_in[7];
    const float* bhh2 = (const float*)d_in[8];
    const float* fcw  = (const float*)d_in[9];
    const float* fcb  = (const float*)d_in[10];
    float* out = (float*)d_out;

    const int grid = (4096 + BG - 1) / BG;   // 293
    lstm_fused<<<grid, NT>>>(x, wih1, whh1, bih1, bhh1,
                             wih2, whh2, bih2, bhh2, fcw, fcb, out);
}